// round 1
// baseline (speedup 1.0000x reference)
#include <cuda_runtime.h>
#include <math.h>

#define NN 50000
#define NE 800000
#define FI 128
#define FH 256

// ---------------- scratch (device globals: allocation-free) ----------------
__device__ float g_h[NN * FH];
__device__ float g_tmp[NN * FH];
__device__ float g_agg[NN * FH];
__device__ float g_hid0[NN * FH];
__device__ float g_hid1[NN * FH];
__device__ float g_dovF[NN], g_divF[NN];
__device__ float g_dov1[NN], g_div1[NN];
__device__ float g_dov2[NN], g_div2[NN];
__device__ float g_m1[NN], g_m2[NN];
__device__ float g_scores[NN];
__device__ unsigned g_keys[NN];
__device__ int g_rowstart[NN + 1];
__device__ int g_rowoff[NN];
__device__ int g_csrsrc[NE];
__device__ int g_hist[256];
__device__ unsigned g_prefix;
__device__ int g_kremain;

// ---------------- helpers ----------------
__device__ __forceinline__ unsigned f2k(float f) {
    unsigned u = __float_as_uint(f);
    return (u & 0x80000000u) ? ~u : (u | 0x80000000u);
}

// ---------------- init / CSR build ----------------
__global__ void zero_init_kernel() {
    int i = blockIdx.x * blockDim.x + threadIdx.x;
    if (i < NN) {
        g_dovF[i] = 0.f; g_divF[i] = 0.f;
        g_dov1[i] = 0.f; g_div1[i] = 0.f;
        g_dov2[i] = 0.f; g_div2[i] = 0.f;
        g_rowoff[i] = 0;
    }
}

__global__ void hist_dst_kernel(const int* __restrict__ dst) {
    int e = blockIdx.x * blockDim.x + threadIdx.x;
    if (e < NE) atomicAdd(&g_rowoff[dst[e]], 1);
}

__global__ void scan_counts_kernel() {
    __shared__ int sh[1024];
    int tid = threadIdx.x;
    int carry = 0;
    for (int base = 0; base < NN; base += 1024) {
        int i = base + tid;
        int v = (i < NN) ? g_rowoff[i] : 0;
        int x = v;
        for (int off = 1; off < 1024; off <<= 1) {
            sh[tid] = x; __syncthreads();
            if (tid >= off) x += sh[tid - off];
            __syncthreads();
        }
        if (i < NN) g_rowstart[i] = carry + x - v;  // exclusive prefix
        sh[tid] = x; __syncthreads();
        carry += sh[1023];
        __syncthreads();
    }
    if (tid == 0) g_rowstart[NN] = carry;
}

__global__ void copy_off_kernel() {
    int i = blockIdx.x * blockDim.x + threadIdx.x;
    if (i < NN) g_rowoff[i] = g_rowstart[i];
}

__global__ void scatter_kernel(const int* __restrict__ src, const int* __restrict__ dst) {
    int e = blockIdx.x * blockDim.x + threadIdx.x;
    if (e < NE) {
        int d = dst[e];
        int pos = atomicAdd(&g_rowoff[d], 1);
        g_csrsrc[pos] = src[e];
    }
}

// ---------------- degrees ----------------
__global__ void deg_edge_kernel(const int* __restrict__ src, const int* __restrict__ dst,
                                const float* __restrict__ m,
                                float* __restrict__ degO, float* __restrict__ degI) {
    int e = blockIdx.x * blockDim.x + threadIdx.x;
    if (e >= NE) return;
    int s = src[e], d = dst[e];
    float w = m ? m[s] * m[d] : 1.f;
    if (w != 0.f) {
        atomicAdd(&degO[s], w);
        atomicAdd(&degI[d], w);
    }
}

__global__ void fin_deg_kernel(float* __restrict__ dov, float* __restrict__ divv,
                               const float* __restrict__ m) {
    int i = blockIdx.x * blockDim.x + threadIdx.x;
    if (i >= NN) return;
    float o = 1.f / sqrtf(fmaxf(dov[i], 1.f));
    dov[i] = m ? o * m[i] : o;
    divv[i] = 1.f / sqrtf(fmaxf(divv[i], 1.f));
}

// ---------------- rowwise scale (optionally + skip) ----------------
__global__ void scale_rows_kernel(const float* __restrict__ a, const float* __restrict__ skip,
                                  const float* __restrict__ s, float* __restrict__ o, int f4) {
    int idx = blockIdx.x * blockDim.x + threadIdx.x;
    int total = NN * f4;
    if (idx >= total) return;
    int i = idx / f4;
    float4 v = ((const float4*)a)[idx];
    if (skip) {
        float4 w = ((const float4*)skip)[idx];
        v.x += w.x; v.y += w.y; v.z += w.z; v.w += w.w;
    }
    float sc = s[i];
    v.x *= sc; v.y *= sc; v.z *= sc; v.w *= sc;
    ((float4*)o)[idx] = v;
}

// ---------------- CSR aggregation: out[d] = (sum_src tmp[src]) * div[d] (+bias) ----------------
__global__ void agg_csr_kernel(const float* __restrict__ tmp, float* __restrict__ out,
                               const float* __restrict__ divv, const float* __restrict__ bias,
                               int F) {
    int node = blockIdx.x;
    int f = threadIdx.x;
    int s = g_rowstart[node], e = g_rowstart[node + 1];
    __shared__ int sidx[64];
    float acc = 0.f;
    for (int b = s; b < e; b += 64) {
        int nn = min(64, e - b);
        __syncthreads();
        if (f < nn) sidx[f] = g_csrsrc[b + f];
        __syncthreads();
        int k = 0;
        for (; k + 4 <= nn; k += 4) {
            acc += tmp[(size_t)sidx[k] * F + f];
            acc += tmp[(size_t)sidx[k + 1] * F + f];
            acc += tmp[(size_t)sidx[k + 2] * F + f];
            acc += tmp[(size_t)sidx[k + 3] * F + f];
        }
        for (; k < nn; k++) acc += tmp[(size_t)sidx[k] * F + f];
    }
    float v = acc * divv[node];
    if (bias) v += bias[f];
    out[(size_t)node * F + f] = v;
}

// ---------------- SGEMM: C = act((A (+Askip)) @ B + bias) * rowmul ----------------
// 128x128 block tile, 256 threads, 8x8 microtile, K step 8.
__global__ void sgemm_kernel(const float* __restrict__ A, const float* __restrict__ Askip,
                             const float* __restrict__ B, float* __restrict__ C,
                             int M, int K, int Ncols,
                             const float* __restrict__ bias,
                             const float* __restrict__ rowmul, int act) {
    __shared__ __align__(16) float As[8][128];
    __shared__ __align__(16) float Bs[8][128];
    int t = threadIdx.x;
    int m0 = blockIdx.y * 128;
    int n0 = blockIdx.x * 128;
    int ty = t >> 4, tx = t & 15;
    int ar = t >> 1, ac = (t & 1) * 4;
    int br = t >> 5, bc = (t & 31) * 4;
    float acc[8][8];
#pragma unroll
    for (int i = 0; i < 8; i++)
#pragma unroll
        for (int j = 0; j < 8; j++) acc[i][j] = 0.f;

    int arow = m0 + ar;
    for (int k0 = 0; k0 < K; k0 += 8) {
        float4 va = make_float4(0.f, 0.f, 0.f, 0.f);
        if (arow < M) {
            va = *(const float4*)(A + (size_t)arow * K + k0 + ac);
            if (Askip) {
                float4 vs = *(const float4*)(Askip + (size_t)arow * K + k0 + ac);
                va.x += vs.x; va.y += vs.y; va.z += vs.z; va.w += vs.w;
            }
        }
        float4 vb = *(const float4*)(B + (size_t)(k0 + br) * Ncols + n0 + bc);
        __syncthreads();
        As[ac + 0][ar] = va.x;
        As[ac + 1][ar] = va.y;
        As[ac + 2][ar] = va.z;
        As[ac + 3][ar] = va.w;
        *(float4*)(&Bs[br][bc]) = vb;
        __syncthreads();
#pragma unroll
        for (int kk = 0; kk < 8; kk++) {
            float a[8], b[8];
            *(float4*)(a)     = *(const float4*)(&As[kk][ty * 8]);
            *(float4*)(a + 4) = *(const float4*)(&As[kk][ty * 8 + 4]);
            *(float4*)(b)     = *(const float4*)(&Bs[kk][tx * 8]);
            *(float4*)(b + 4) = *(const float4*)(&Bs[kk][tx * 8 + 4]);
#pragma unroll
            for (int i = 0; i < 8; i++)
#pragma unroll
                for (int j = 0; j < 8; j++) acc[i][j] = fmaf(a[i], b[j], acc[i][j]);
        }
    }
    // epilogue
#pragma unroll
    for (int i = 0; i < 8; i++) {
        int row = m0 + ty * 8 + i;
        if (row >= M) continue;
        float rm = rowmul ? rowmul[row] : 1.f;
        float v[8];
#pragma unroll
        for (int j = 0; j < 8; j++) {
            int col = n0 + tx * 8 + j;
            float x = acc[i][j];
            if (bias) x += bias[col];
            if (act) x = fmaxf(x, 0.f);
            v[j] = x * rm;
        }
        float* cp = C + (size_t)row * Ncols + n0 + tx * 8;
        *(float4*)(cp)     = make_float4(v[0], v[1], v[2], v[3]);
        *(float4*)(cp + 4) = make_float4(v[4], v[5], v[6], v[7]);
    }
}

// ---------------- scores: s = sigmoid(h . Wp + bp); key for top-k ----------------
__global__ void scores_kernel(const float* __restrict__ h, const float* __restrict__ Wp,
                              const float* __restrict__ bp, const float* __restrict__ m) {
    int warp = (blockIdx.x * blockDim.x + threadIdx.x) >> 5;
    int lane = threadIdx.x & 31;
    if (warp >= NN) return;
    const float* hr = h + (size_t)warp * FH;
    float z = 0.f;
#pragma unroll
    for (int j = 0; j < 8; j++) z = fmaf(hr[lane + 32 * j], Wp[lane + 32 * j], z);
#pragma unroll
    for (int off = 16; off; off >>= 1) z += __shfl_xor_sync(0xFFFFFFFFu, z, off);
    if (lane == 0) {
        z += bp[0];
        float s = 1.f / (1.f + expf(-z));
        g_scores[warp] = s;
        float kin = (m && m[warp] == 0.f) ? -1e9f : s;
        g_keys[warp] = f2k(kin);
    }
}

// ---------------- exact top-k via 4-pass radix select ----------------
__global__ void rs_init_kernel(int K) {
    if (threadIdx.x == 0) { g_prefix = 0u; g_kremain = K; }
    if (threadIdx.x < 256) g_hist[threadIdx.x] = 0;
}

__global__ void rs_hist_kernel(int shift) {
    int i = blockIdx.x * blockDim.x + threadIdx.x;
    if (i >= NN) return;
    unsigned k = g_keys[i];
    bool ok = (shift == 24) || ((k >> (shift + 8)) == (g_prefix >> (shift + 8)));
    if (ok) atomicAdd(&g_hist[(k >> shift) & 255], 1);
}

__global__ void rs_pick_kernel(int shift) {
    if (threadIdx.x == 0) {
        int kr = g_kremain;
        unsigned pref = g_prefix;
        for (int b = 255; b >= 0; b--) {
            int c = g_hist[b];
            if (c >= kr) { g_prefix = pref | (((unsigned)b) << shift); break; }
            kr -= c;
        }
        g_kremain = kr;
    }
    __syncthreads();
    if (threadIdx.x < 256) g_hist[threadIdx.x] = 0;
}

__global__ void build_mask_kernel(float* __restrict__ m) {
    int i = blockIdx.x * blockDim.x + threadIdx.x;
    if (i >= NN) return;
    float sel = (g_keys[i] >= g_prefix) ? 1.f : 0.f;
    m[i] = sel;
    g_scores[i] *= sel;  // gate factor = score * mask
}

// ---------------- host orchestration ----------------
static inline void* sym(const void* s) {
    void* p = nullptr;
    cudaGetSymbolAddress(&p, (const void*)s);
    return p;
}

extern "C" void kernel_launch(void* const* d_in, const int* in_sizes, int n_in,
                              void* d_out, int out_size) {
    const float* features = (const float*)d_in[0];
    const int* src = (const int*)d_in[1];
    const int* dst = (const int*)d_in[2];
    const float* W_embed = (const float*)d_in[3];
    const float* b_embed = (const float*)d_in[4];
    const float* W_enc0 = (const float*)d_in[5];
    const float* b_enc0 = (const float*)d_in[6];
    const float* W_enc1 = (const float*)d_in[7];
    const float* b_enc1 = (const float*)d_in[8];
    const float* W_p0 = (const float*)d_in[9];
    const float* b_p0 = (const float*)d_in[10];
    const float* W_p1 = (const float*)d_in[11];
    const float* b_p1 = (const float*)d_in[12];
    const float* W_bot = (const float*)d_in[13];
    const float* b_bot = (const float*)d_in[14];
    const float* W_dec0 = (const float*)d_in[15];
    const float* b_dec0 = (const float*)d_in[16];
    const float* W_dec1 = (const float*)d_in[17];
    const float* b_dec1 = (const float*)d_in[18];
    float* out = (float*)d_out;

    float* p_h    = (float*)sym(g_h);
    float* p_tmp  = (float*)sym(g_tmp);
    float* p_agg  = (float*)sym(g_agg);
    float* p_hid0 = (float*)sym(g_hid0);
    float* p_hid1 = (float*)sym(g_hid1);
    float* p_dovF = (float*)sym(g_dovF);
    float* p_divF = (float*)sym(g_divF);
    float* p_dov1 = (float*)sym(g_dov1);
    float* p_div1 = (float*)sym(g_div1);
    float* p_dov2 = (float*)sym(g_dov2);
    float* p_div2 = (float*)sym(g_div2);
    float* p_m1   = (float*)sym(g_m1);
    float* p_m2   = (float*)sym(g_m2);
    float* p_sc   = (float*)sym(g_scores);

    const int TB = 256;
    const int NB_N = (NN + TB - 1) / TB;
    const int NB_E = (NE + TB - 1) / TB;
    const int M = NN;
    dim3 gemm_grid_256(2, (M + 127) / 128);
    dim3 gemm_grid_128(1, (M + 127) / 128);

    // init + CSR build (once per launch, reused by all 6 layers)
    zero_init_kernel<<<NB_N, TB>>>();
    hist_dst_kernel<<<NB_E, TB>>>(dst);
    scan_counts_kernel<<<1, 1024>>>();
    copy_off_kernel<<<NB_N, TB>>>();
    scatter_kernel<<<NB_E, TB>>>(src, dst);

    // full-graph degrees
    deg_edge_kernel<<<NB_E, TB>>>(src, dst, nullptr, p_dovF, p_divF);
    fin_deg_kernel<<<NB_N, TB>>>(p_dovF, p_divF, nullptr);

    // L0 embed: aggregate features (128-dim) first, then 128->256 GEMM
    scale_rows_kernel<<<(NN * (FI / 4) + TB - 1) / TB, TB>>>(features, nullptr, p_dovF, p_tmp, FI / 4);
    agg_csr_kernel<<<NN, FI>>>(p_tmp, p_agg, p_divF, nullptr, FI);
    sgemm_kernel<<<gemm_grid_256, TB>>>(p_agg, nullptr, W_embed, p_h, M, FI, FH, b_embed, nullptr, 1);

    // L1 enc0 (full graph) -> hidden0
    scale_rows_kernel<<<(NN * (FH / 4) + TB - 1) / TB, TB>>>(p_h, nullptr, p_dovF, p_tmp, FH / 4);
    agg_csr_kernel<<<NN, FH>>>(p_tmp, p_agg, p_divF, nullptr, FH);
    sgemm_kernel<<<gemm_grid_256, TB>>>(p_agg, nullptr, W_enc0, p_hid0, M, FH, FH, b_enc0, nullptr, 1);

    // pool 0: scores + exact top-25000 + gate
    scores_kernel<<<(NN + 7) / 8, TB>>>(p_hid0, W_p0, b_p0, nullptr);
    rs_init_kernel<<<1, 256>>>(25000);
    {
        const int shifts[4] = {24, 16, 8, 0};
        for (int r = 0; r < 4; r++) {
            rs_hist_kernel<<<NB_N, TB>>>(shifts[r]);
            rs_pick_kernel<<<1, 256>>>(shifts[r]);
        }
    }
    build_mask_kernel<<<NB_N, TB>>>(p_m1);
    scale_rows_kernel<<<(NN * (FH / 4) + TB - 1) / TB, TB>>>(p_hid0, nullptr, p_sc, p_h, FH / 4);

    // masked degrees for level-1 subgraph
    deg_edge_kernel<<<NB_E, TB>>>(src, dst, p_m1, p_dov1, p_div1);
    fin_deg_kernel<<<NB_N, TB>>>(p_dov1, p_div1, p_m1);

    // L2 enc1 (m1 subgraph) -> hidden1
    scale_rows_kernel<<<(NN * (FH / 4) + TB - 1) / TB, TB>>>(p_h, nullptr, p_dov1, p_tmp, FH / 4);
    agg_csr_kernel<<<NN, FH>>>(p_tmp, p_agg, p_div1, nullptr, FH);
    sgemm_kernel<<<gemm_grid_256, TB>>>(p_agg, nullptr, W_enc1, p_hid1, M, FH, FH, b_enc1, p_m1, 1);

    // pool 1: scores + exact top-12500 + gate
    scores_kernel<<<(NN + 7) / 8, TB>>>(p_hid1, W_p1, b_p1, p_m1);
    rs_init_kernel<<<1, 256>>>(12500);
    {
        const int shifts[4] = {24, 16, 8, 0};
        for (int r = 0; r < 4; r++) {
            rs_hist_kernel<<<NB_N, TB>>>(shifts[r]);
            rs_pick_kernel<<<1, 256>>>(shifts[r]);
        }
    }
    build_mask_kernel<<<NB_N, TB>>>(p_m2);
    scale_rows_kernel<<<(NN * (FH / 4) + TB - 1) / TB, TB>>>(p_hid1, nullptr, p_sc, p_h, FH / 4);

    // masked degrees for level-2 subgraph
    deg_edge_kernel<<<NB_E, TB>>>(src, dst, p_m2, p_dov2, p_div2);
    fin_deg_kernel<<<NB_N, TB>>>(p_dov2, p_div2, p_m2);

    // L3 bottom (m2 subgraph)
    scale_rows_kernel<<<(NN * (FH / 4) + TB - 1) / TB, TB>>>(p_h, nullptr, p_dov2, p_tmp, FH / 4);
    agg_csr_kernel<<<NN, FH>>>(p_tmp, p_agg, p_div2, nullptr, FH);
    sgemm_kernel<<<gemm_grid_256, TB>>>(p_agg, nullptr, W_bot, p_h, M, FH, FH, b_bot, p_m2, 1);

    // L4 dec0: (h + hidden1) on m1 subgraph
    scale_rows_kernel<<<(NN * (FH / 4) + TB - 1) / TB, TB>>>(p_h, p_hid1, p_dov1, p_tmp, FH / 4);
    agg_csr_kernel<<<NN, FH>>>(p_tmp, p_agg, p_div1, nullptr, FH);
    sgemm_kernel<<<gemm_grid_256, TB>>>(p_agg, nullptr, W_dec0, p_h, M, FH, FH, b_dec0, p_m1, 1);

    // L5 dec1: GEMM first (256->128), then 128-dim aggregation; no act.
    // y = ((h + hidden0) @ W_dec1) * dovF ; out = agg(y) * divF + b_dec1
    sgemm_kernel<<<gemm_grid_128, TB>>>(p_h, p_hid0, W_dec1, p_tmp, M, FH, FI, nullptr, p_dovF, 0);
    agg_csr_kernel<<<NN, FI>>>(p_tmp, out, p_divF, b_dec1, FI);
}

// round 3
// speedup vs baseline: 1.5445x; 1.5445x over previous
#include <cuda_runtime.h>
#include <cuda_fp16.h>
#include <math.h>
#include <stdint.h>

#define NN 50000
#define NE 800000
#define FI 128
#define FH 256

// ---------------- scratch (device globals: allocation-free) ----------------
__device__ __align__(16) float g_h[NN * FH];
__device__ __align__(16) float g_tmp[NN * FH];
__device__ __align__(16) float g_hid0[NN * FH];
__device__ __align__(16) float g_hid1[NN * FH];
__device__ __align__(16) __half g_ahi[NN * FH];
__device__ __align__(16) __half g_alo[NN * FH];
__device__ __align__(16) __half g_bhi[FH * FH];
__device__ __align__(16) __half g_blo[FH * FH];
__device__ float g_dovF[NN], g_divF[NN];
__device__ float g_dov1[NN], g_div1[NN];
__device__ float g_dov2[NN], g_div2[NN];
__device__ float g_m1[NN], g_m2[NN];
__device__ float g_scores[NN];
__device__ float g_comb[NN];
__device__ unsigned g_keys[NN];
__device__ int g_rowstart[NN + 1];
__device__ int g_rowoff[NN];
__device__ int g_csrsrc[NE];
__device__ int g_hist[256];
__device__ unsigned g_prefix;
__device__ int g_kremain;

// ---------------- small helpers ----------------
__device__ __forceinline__ unsigned f2k(float f) {
    unsigned u = __float_as_uint(f);
    return (u & 0x80000000u) ? ~u : (u | 0x80000000u);
}
__device__ __forceinline__ void split2(float v, __half& hi, __half& lo) {
    hi = __float2half_rn(v);
    lo = __float2half_rn(v - __half2float(hi));
}

// ---------------- init / CSR build ----------------
__global__ void zero_init_kernel() {
    int i = blockIdx.x * blockDim.x + threadIdx.x;
    if (i < NN) {
        g_dovF[i] = 0.f; g_divF[i] = 0.f;
        g_dov1[i] = 0.f; g_div1[i] = 0.f;
        g_dov2[i] = 0.f; g_div2[i] = 0.f;
        g_rowoff[i] = 0;
    }
}
__global__ void hist_dst_kernel(const int* __restrict__ dst) {
    int e = blockIdx.x * blockDim.x + threadIdx.x;
    if (e < NE) atomicAdd(&g_rowoff[dst[e]], 1);
}
__global__ void scan_counts_kernel() {
    __shared__ int sh[1024];
    int tid = threadIdx.x;
    int carry = 0;
    for (int base = 0; base < NN; base += 1024) {
        int i = base + tid;
        int v = (i < NN) ? g_rowoff[i] : 0;
        int x = v;
        for (int off = 1; off < 1024; off <<= 1) {
            sh[tid] = x; __syncthreads();
            if (tid >= off) x += sh[tid - off];
            __syncthreads();
        }
        if (i < NN) g_rowstart[i] = carry + x - v;
        sh[tid] = x; __syncthreads();
        carry += sh[1023];
        __syncthreads();
    }
    if (tid == 0) g_rowstart[NN] = carry;
}
__global__ void copy_off_kernel() {
    int i = blockIdx.x * blockDim.x + threadIdx.x;
    if (i < NN) g_rowoff[i] = g_rowstart[i];
}
__global__ void scatter_kernel(const int* __restrict__ src, const int* __restrict__ dst) {
    int e = blockIdx.x * blockDim.x + threadIdx.x;
    if (e < NE) {
        int pos = atomicAdd(&g_rowoff[dst[e]], 1);
        g_csrsrc[pos] = src[e];
    }
}

// ---------------- degrees ----------------
__global__ void deg_edge_kernel(const int* __restrict__ src, const int* __restrict__ dst,
                                const float* __restrict__ m,
                                float* __restrict__ degO, float* __restrict__ degI) {
    int e = blockIdx.x * blockDim.x + threadIdx.x;
    if (e >= NE) return;
    int s = src[e], d = dst[e];
    float w = m ? m[s] * m[d] : 1.f;
    if (w != 0.f) {
        atomicAdd(&degO[s], w);
        atomicAdd(&degI[d], w);
    }
}
__global__ void fin_deg_kernel(float* __restrict__ dov, float* __restrict__ divv,
                               const float* __restrict__ m) {
    int i = blockIdx.x * blockDim.x + threadIdx.x;
    if (i >= NN) return;
    float o = 1.f / sqrtf(fmaxf(dov[i], 1.f));
    dov[i] = m ? o * m[i] : o;
    divv[i] = 1.f / sqrtf(fmaxf(divv[i], 1.f));
}

// comb[i] = scores[i] * dov[i]
__global__ void comb_kernel(const float* __restrict__ s, const float* __restrict__ dov,
                            float* __restrict__ c) {
    int i = blockIdx.x * blockDim.x + threadIdx.x;
    if (i < NN) c[i] = s[i] * dov[i];
}

// add: o = a + b (fp32, float4)
__global__ void add_kernel(const float* __restrict__ a, const float* __restrict__ b,
                           float* __restrict__ o) {
    int idx = blockIdx.x * blockDim.x + threadIdx.x;
    if (idx >= NN * (FH / 4)) return;
    float4 va = ((const float4*)a)[idx];
    float4 vb = ((const float4*)b)[idx];
    va.x += vb.x; va.y += vb.y; va.z += vb.z; va.w += vb.w;
    ((float4*)o)[idx] = va;
}

// split_add: (a+b) -> fp16 hi/lo split arrays
__global__ void split_add_kernel(const float* __restrict__ a, const float* __restrict__ b,
                                 __half* __restrict__ hi, __half* __restrict__ lo) {
    int idx = blockIdx.x * blockDim.x + threadIdx.x;
    if (idx >= NN * FH) return;
    float v = a[idx] + b[idx];
    split2(v, hi[idx], lo[idx]);
}

// weight prep: B[n*K+k] = split(W[k*N+n])
__global__ void wprep_kernel(const float* __restrict__ W, __half* __restrict__ bhi,
                             __half* __restrict__ blo, int K, int Ncols) {
    int idx = blockIdx.x * blockDim.x + threadIdx.x;
    if (idx >= K * Ncols) return;
    int k = idx / Ncols, n = idx % Ncols;
    split2(W[idx], bhi[n * K + k], blo[n * K + k]);
}

// ---------------- CSR aggregation ----------------
__global__ void agg_half_kernel(const float* __restrict__ x, const float* __restrict__ smul,
                                const float* __restrict__ divv,
                                __half* __restrict__ ohi, __half* __restrict__ olo, int F) {
    int node = blockIdx.x;
    int f = threadIdx.x;
    int s = g_rowstart[node], e = g_rowstart[node + 1];
    __shared__ int sidx[64];
    __shared__ float sval[64];
    float acc = 0.f;
    for (int b = s; b < e; b += 64) {
        int nn = min(64, e - b);
        __syncthreads();
        if (f < nn) {
            int si = g_csrsrc[b + f];
            sidx[f] = si;
            sval[f] = smul ? smul[si] : 1.f;
        }
        __syncthreads();
        for (int k = 0; k < nn; k++) {
            float sc = sval[k];
            if (sc != 0.f) acc = fmaf(x[(size_t)sidx[k] * F + f], sc, acc);
        }
    }
    float v = acc * divv[node];
    size_t o = (size_t)node * F + f;
    split2(v, ohi[o], olo[o]);
}

__global__ void agg_float_kernel(const float* __restrict__ x, const float* __restrict__ divv,
                                 const float* __restrict__ bias, float* __restrict__ out, int F) {
    int node = blockIdx.x;
    int f = threadIdx.x;
    int s = g_rowstart[node], e = g_rowstart[node + 1];
    __shared__ int sidx[64];
    float acc = 0.f;
    for (int b = s; b < e; b += 64) {
        int nn = min(64, e - b);
        __syncthreads();
        if (f < nn) sidx[f] = g_csrsrc[b + f];
        __syncthreads();
        for (int k = 0; k < nn; k++) acc += x[(size_t)sidx[k] * F + f];
    }
    out[(size_t)node * F + f] = acc * divv[node] + bias[f];
}

// ---------------- HMMA (mma.sync) fp16-split GEMM ----------------
// C[M,N] = act( (Ahi+Alo)[M,K] @ (Bhi+Blo)[N,K]^T + bias ) * rowmul
// 3 passes: Ah*Bh + Ah*Bl + Al*Bh ; fp32 accumulate in registers.
// Block 256 thr (8 warps = 2M x 4N), tile 128x128, warp tile 64x32, kc=64.
#define SMS 72  // smem row stride in halfs (padded; conflict-free frag loads)
#define GEMM_SMEM (4 * 128 * SMS * 2)

#define MMA168(d, a, b) \
    asm volatile( \
        "mma.sync.aligned.m16n8k16.row.col.f32.f16.f16.f32 " \
        "{%0,%1,%2,%3}, {%4,%5,%6,%7}, {%8,%9}, {%0,%1,%2,%3};" \
        : "+f"((d)[0]), "+f"((d)[1]), "+f"((d)[2]), "+f"((d)[3]) \
        : "r"((a)[0]), "r"((a)[1]), "r"((a)[2]), "r"((a)[3]), \
          "r"((b)[0]), "r"((b)[1]))

__global__ void __launch_bounds__(256, 2)
gemm_hmma_kernel(const __half* __restrict__ Ahi, const __half* __restrict__ Alo,
                 const __half* __restrict__ Bhi, const __half* __restrict__ Blo,
                 float* __restrict__ C, int M, int K, int N,
                 const float* __restrict__ bias, const float* __restrict__ rowmul, int act) {
    extern __shared__ __half sm[];
    __half* sAh = sm;
    __half* sAl = sAh + 128 * SMS;
    __half* sBh = sAl + 128 * SMS;
    __half* sBl = sBh + 128 * SMS;
    int t = threadIdx.x;
    int m0 = blockIdx.y * 128, n0 = blockIdx.x * 128;
    int w = t >> 5, lane = t & 31;
    int g = lane >> 2, tig = lane & 3;
    int wm = (w & 1) * 64, wn = (w >> 1) * 32;

    float acc[4][4][4];
#pragma unroll
    for (int i = 0; i < 4; i++)
#pragma unroll
        for (int j = 0; j < 4; j++)
#pragma unroll
            for (int k = 0; k < 4; k++) acc[i][j][k] = 0.f;

    for (int kc = 0; kc < K; kc += 64) {
        for (int idx = t; idx < 1024; idx += 256) {
            int r = idx >> 3, c = idx & 7;
            uint4 vh = make_uint4(0, 0, 0, 0), vl = make_uint4(0, 0, 0, 0);
            if (m0 + r < M) {
                size_t go = (size_t)(m0 + r) * K + kc + c * 8;
                vh = *(const uint4*)(Ahi + go);
                vl = *(const uint4*)(Alo + go);
            }
            *(uint4*)(sAh + r * SMS + c * 8) = vh;
            *(uint4*)(sAl + r * SMS + c * 8) = vl;
            size_t gb = (size_t)(n0 + r) * K + kc + c * 8;
            *(uint4*)(sBh + r * SMS + c * 8) = *(const uint4*)(Bhi + gb);
            *(uint4*)(sBl + r * SMS + c * 8) = *(const uint4*)(Blo + gb);
        }
        __syncthreads();
#pragma unroll
        for (int ks = 0; ks < 4; ks++) {
            int kb = ks * 16 + tig * 2;
            uint32_t ar[4][4], br[4][2], br2[4][2];
#pragma unroll
            for (int mi = 0; mi < 4; mi++) {
                int r = wm + mi * 16 + g;
                ar[mi][0] = *(const uint32_t*)(sAh + r * SMS + kb);
                ar[mi][1] = *(const uint32_t*)(sAh + (r + 8) * SMS + kb);
                ar[mi][2] = *(const uint32_t*)(sAh + r * SMS + kb + 8);
                ar[mi][3] = *(const uint32_t*)(sAh + (r + 8) * SMS + kb + 8);
            }
#pragma unroll
            for (int ni = 0; ni < 4; ni++) {
                int r = wn + ni * 8 + g;
                br[ni][0]  = *(const uint32_t*)(sBh + r * SMS + kb);
                br[ni][1]  = *(const uint32_t*)(sBh + r * SMS + kb + 8);
                br2[ni][0] = *(const uint32_t*)(sBl + r * SMS + kb);
                br2[ni][1] = *(const uint32_t*)(sBl + r * SMS + kb + 8);
            }
            // pass hh + hl (Ah against Bh and Bl)
#pragma unroll
            for (int mi = 0; mi < 4; mi++)
#pragma unroll
                for (int ni = 0; ni < 4; ni++) {
                    MMA168(acc[mi][ni], ar[mi], br[ni]);
                    MMA168(acc[mi][ni], ar[mi], br2[ni]);
                }
            // pass lh: reload A from lo into ar
#pragma unroll
            for (int mi = 0; mi < 4; mi++) {
                int r = wm + mi * 16 + g;
                ar[mi][0] = *(const uint32_t*)(sAl + r * SMS + kb);
                ar[mi][1] = *(const uint32_t*)(sAl + (r + 8) * SMS + kb);
                ar[mi][2] = *(const uint32_t*)(sAl + r * SMS + kb + 8);
                ar[mi][3] = *(const uint32_t*)(sAl + (r + 8) * SMS + kb + 8);
            }
#pragma unroll
            for (int mi = 0; mi < 4; mi++)
#pragma unroll
                for (int ni = 0; ni < 4; ni++)
                    MMA168(acc[mi][ni], ar[mi], br[ni]);
        }
        __syncthreads();
    }

    // epilogue
#pragma unroll
    for (int mi = 0; mi < 4; mi++) {
#pragma unroll
        for (int half8 = 0; half8 < 2; half8++) {
            int row = m0 + wm + mi * 16 + g + half8 * 8;
            if (row >= M) continue;
            float rm = rowmul ? rowmul[row] : 1.f;
#pragma unroll
            for (int ni = 0; ni < 4; ni++) {
                int col = n0 + wn + ni * 8 + tig * 2;
                float v0 = acc[mi][ni][half8 * 2 + 0];
                float v1 = acc[mi][ni][half8 * 2 + 1];
                if (bias) { v0 += bias[col]; v1 += bias[col + 1]; }
                if (act) { v0 = fmaxf(v0, 0.f); v1 = fmaxf(v1, 0.f); }
                v0 *= rm; v1 *= rm;
                *(float2*)(C + (size_t)row * N + col) = make_float2(v0, v1);
            }
        }
    }
}

// ---------------- scores + exact top-k ----------------
__global__ void scores_kernel(const float* __restrict__ h, const float* __restrict__ Wp,
                              const float* __restrict__ bp, const float* __restrict__ m) {
    int warp = (blockIdx.x * blockDim.x + threadIdx.x) >> 5;
    int lane = threadIdx.x & 31;
    if (warp >= NN) return;
    const float* hr = h + (size_t)warp * FH;
    float z = 0.f;
#pragma unroll
    for (int j = 0; j < 8; j++) z = fmaf(hr[lane + 32 * j], Wp[lane + 32 * j], z);
#pragma unroll
    for (int off = 16; off; off >>= 1) z += __shfl_xor_sync(0xFFFFFFFFu, z, off);
    if (lane == 0) {
        z += bp[0];
        float s = 1.f / (1.f + expf(-z));
        g_scores[warp] = s;
        float kin = (m && m[warp] == 0.f) ? -1e9f : s;
        g_keys[warp] = f2k(kin);
    }
}
__global__ void rs_init_kernel(int K) {
    if (threadIdx.x == 0) { g_prefix = 0u; g_kremain = K; }
    if (threadIdx.x < 256) g_hist[threadIdx.x] = 0;
}
__global__ void rs_hist_kernel(int shift) {
    int i = blockIdx.x * blockDim.x + threadIdx.x;
    if (i >= NN) return;
    unsigned k = g_keys[i];
    bool ok = (shift == 24) || ((k >> (shift + 8)) == (g_prefix >> (shift + 8)));
    if (ok) atomicAdd(&g_hist[(k >> shift) & 255], 1);
}
__global__ void rs_pick_kernel(int shift) {
    if (threadIdx.x == 0) {
        int kr = g_kremain;
        unsigned pref = g_prefix;
        for (int b = 255; b >= 0; b--) {
            int c = g_hist[b];
            if (c >= kr) { g_prefix = pref | (((unsigned)b) << shift); break; }
            kr -= c;
        }
        g_kremain = kr;
    }
    __syncthreads();
    if (threadIdx.x < 256) g_hist[threadIdx.x] = 0;
}
__global__ void build_mask_kernel(float* __restrict__ m) {
    int i = blockIdx.x * blockDim.x + threadIdx.x;
    if (i >= NN) return;
    float sel = (g_keys[i] >= g_prefix) ? 1.f : 0.f;
    m[i] = sel;
    g_scores[i] *= sel;
}

// ---------------- host orchestration ----------------
static inline void* sym(const void* s) {
    void* p = nullptr;
    cudaGetSymbolAddress(&p, (const void*)s);
    return p;
}

extern "C" void kernel_launch(void* const* d_in, const int* in_sizes, int n_in,
                              void* d_out, int out_size) {
    const float* features = (const float*)d_in[0];
    const int* src = (const int*)d_in[1];
    const int* dst = (const int*)d_in[2];
    const float* W_embed = (const float*)d_in[3];
    const float* b_embed = (const float*)d_in[4];
    const float* W_enc0 = (const float*)d_in[5];
    const float* b_enc0 = (const float*)d_in[6];
    const float* W_enc1 = (const float*)d_in[7];
    const float* b_enc1 = (const float*)d_in[8];
    const float* W_p0 = (const float*)d_in[9];
    const float* b_p0 = (const float*)d_in[10];
    const float* W_p1 = (const float*)d_in[11];
    const float* b_p1 = (const float*)d_in[12];
    const float* W_bot = (const float*)d_in[13];
    const float* b_bot = (const float*)d_in[14];
    const float* W_dec0 = (const float*)d_in[15];
    const float* b_dec0 = (const float*)d_in[16];
    const float* W_dec1 = (const float*)d_in[17];
    const float* b_dec1 = (const float*)d_in[18];
    float* out = (float*)d_out;

    float* p_h    = (float*)sym(g_h);
    float* p_tmp  = (float*)sym(g_tmp);
    float* p_hid0 = (float*)sym(g_hid0);
    float* p_hid1 = (float*)sym(g_hid1);
    __half* p_ahi = (__half*)sym(g_ahi);
    __half* p_alo = (__half*)sym(g_alo);
    __half* p_bhi = (__half*)sym(g_bhi);
    __half* p_blo = (__half*)sym(g_blo);
    float* p_dovF = (float*)sym(g_dovF);
    float* p_divF = (float*)sym(g_divF);
    float* p_dov1 = (float*)sym(g_dov1);
    float* p_div1 = (float*)sym(g_div1);
    float* p_dov2 = (float*)sym(g_dov2);
    float* p_div2 = (float*)sym(g_div2);
    float* p_m1   = (float*)sym(g_m1);
    float* p_m2   = (float*)sym(g_m2);
    float* p_sc   = (float*)sym(g_scores);
    float* p_comb = (float*)sym(g_comb);

    cudaFuncSetAttribute(gemm_hmma_kernel, cudaFuncAttributeMaxDynamicSharedMemorySize,
                         GEMM_SMEM);

    const int TB = 256;
    const int NB_N = (NN + TB - 1) / TB;
    const int NB_E = (NE + TB - 1) / TB;
    const int M = NN;
    dim3 grid256(2, (M + 127) / 128);  // N=256
    dim3 grid128(1, (M + 127) / 128);  // N=128

    // CSR build + full-graph degrees
    zero_init_kernel<<<NB_N, TB>>>();
    hist_dst_kernel<<<NB_E, TB>>>(dst);
    scan_counts_kernel<<<1, 1024>>>();
    copy_off_kernel<<<NB_N, TB>>>();
    scatter_kernel<<<NB_E, TB>>>(src, dst);
    deg_edge_kernel<<<NB_E, TB>>>(src, dst, nullptr, p_dovF, p_divF);
    fin_deg_kernel<<<NB_N, TB>>>(p_dovF, p_divF, nullptr);

    // L0 embed: agg(features * dovF) -> fp16 split; GEMM 128->256
    agg_half_kernel<<<NN, FI>>>(features, p_dovF, p_divF, p_ahi, p_alo, FI);
    wprep_kernel<<<(FI * FH) / TB, TB>>>(W_embed, p_bhi, p_blo, FI, FH);
    gemm_hmma_kernel<<<grid256, 256, GEMM_SMEM>>>(p_ahi, p_alo, p_bhi, p_blo, p_h,
                                                  M, FI, FH, b_embed, nullptr, 1);

    // L1 enc0 -> hid0
    agg_half_kernel<<<NN, FH>>>(p_h, p_dovF, p_divF, p_ahi, p_alo, FH);
    wprep_kernel<<<(FH * FH) / TB, TB>>>(W_enc0, p_bhi, p_blo, FH, FH);
    gemm_hmma_kernel<<<grid256, 256, GEMM_SMEM>>>(p_ahi, p_alo, p_bhi, p_blo, p_hid0,
                                                  M, FH, FH, b_enc0, nullptr, 1);

    // pool0: top-25000
    scores_kernel<<<(NN + 7) / 8, TB>>>(p_hid0, W_p0, b_p0, nullptr);
    rs_init_kernel<<<1, 256>>>(25000);
    for (int r = 0; r < 4; r++) {
        int sh = 24 - 8 * r;
        rs_hist_kernel<<<NB_N, TB>>>(sh);
        rs_pick_kernel<<<1, 256>>>(sh);
    }
    build_mask_kernel<<<NB_N, TB>>>(p_m1);
    deg_edge_kernel<<<NB_E, TB>>>(src, dst, p_m1, p_dov1, p_div1);
    fin_deg_kernel<<<NB_N, TB>>>(p_dov1, p_div1, p_m1);
    comb_kernel<<<NB_N, TB>>>(p_sc, p_dov1, p_comb);

    // L2 enc1 (m1 subgraph, gate folded into comb) -> hid1
    agg_half_kernel<<<NN, FH>>>(p_hid0, p_comb, p_div1, p_ahi, p_alo, FH);
    wprep_kernel<<<(FH * FH) / TB, TB>>>(W_enc1, p_bhi, p_blo, FH, FH);
    gemm_hmma_kernel<<<grid256, 256, GEMM_SMEM>>>(p_ahi, p_alo, p_bhi, p_blo, p_hid1,
                                                  M, FH, FH, b_enc1, p_m1, 1);

    // pool1: top-12500
    scores_kernel<<<(NN + 7) / 8, TB>>>(p_hid1, W_p1, b_p1, p_m1);
    rs_init_kernel<<<1, 256>>>(12500);
    for (int r = 0; r < 4; r++) {
        int sh = 24 - 8 * r;
        rs_hist_kernel<<<NB_N, TB>>>(sh);
        rs_pick_kernel<<<1, 256>>>(sh);
    }
    build_mask_kernel<<<NB_N, TB>>>(p_m2);
    deg_edge_kernel<<<NB_E, TB>>>(src, dst, p_m2, p_dov2, p_div2);
    fin_deg_kernel<<<NB_N, TB>>>(p_dov2, p_div2, p_m2);
    comb_kernel<<<NB_N, TB>>>(p_sc, p_dov2, p_comb);

    // L3 bottom (m2 subgraph) -> g_h
    agg_half_kernel<<<NN, FH>>>(p_hid1, p_comb, p_div2, p_ahi, p_alo, FH);
    wprep_kernel<<<(FH * FH) / TB, TB>>>(W_bot, p_bhi, p_blo, FH, FH);
    gemm_hmma_kernel<<<grid256, 256, GEMM_SMEM>>>(p_ahi, p_alo, p_bhi, p_blo, p_h,
                                                  M, FH, FH, b_bot, p_m2, 1);

    // L4 dec0: agg((h + hid1) * dov1) -> GEMM (rowmul=m1)
    add_kernel<<<(NN * (FH / 4) + TB - 1) / TB, TB>>>(p_h, p_hid1, p_tmp);
    agg_half_kernel<<<NN, FH>>>(p_tmp, p_dov1, p_div1, p_ahi, p_alo, FH);
    wprep_kernel<<<(FH * FH) / TB, TB>>>(W_dec0, p_bhi, p_blo, FH, FH);
    gemm_hmma_kernel<<<grid256, 256, GEMM_SMEM>>>(p_ahi, p_alo, p_bhi, p_blo, p_h,
                                                  M, FH, FH, b_dec0, p_m1, 1);

    // L5 dec1 (GEMM first: 256->128, rowmul=dovF), then agg + bias -> out
    split_add_kernel<<<(NN * FH + TB - 1) / TB, TB>>>(p_h, p_hid0, p_ahi, p_alo);
    wprep_kernel<<<(FH * FI) / TB, TB>>>(W_dec1, p_bhi, p_blo, FH, FI);
    gemm_hmma_kernel<<<grid128, 256, GEMM_SMEM>>>(p_ahi, p_alo, p_bhi, p_blo, p_tmp,
                                                  M, FH, FI, nullptr, p_dovF, 0);
    agg_float_kernel<<<NN, FI>>>(p_tmp, p_divF, b_dec1, out, FI);
}

// round 4
// speedup vs baseline: 2.0291x; 1.3138x over previous
#include <cuda_runtime.h>
#include <cuda_fp16.h>
#include <math.h>
#include <stdint.h>

#define NN 50000
#define NE 800000
#define FI 128
#define FH 256
#define K1 25000
#define K2 12500

// ---------------- scratch (device globals; zero-init, allocation-free) -----
__device__ __align__(16) float g_xa[NN * FH];    // agg out / gemm A
__device__ __align__(16) float g_h[NN * FH];     // gemm0 out / pre-add tmp
__device__ __align__(16) float g_hid0[NN * FH];  // L1 out (full)
__device__ __align__(16) float g_hid1[NN * FH];  // L2 out (scattered; else 0)
__device__ __align__(16) float g_hbot[NN * FH];  // L3 out (scattered; else 0)
__device__ __align__(16) float g_h4[NN * FH];    // L4 out (scattered; else 0)
__device__ __align__(16) float g_wt[327680];     // transposed weights, all 6
__device__ int g_degout[NN];
__device__ int g_degO1[NN], g_degI1[NN], g_degO2[NN], g_degI2[NN];
__device__ float g_comb1[NN], g_dov1[NN], g_div1[NN];
__device__ float g_comb2[NN], g_dov2[NN], g_div2[NN];
__device__ float g_scores[NN];
__device__ unsigned g_keys[NN];
__device__ int g_rowstart[NN + 1];
__device__ int g_rowoff[NN];
__device__ int g_csrsrc[NE];
__device__ int g_alist1[NN], g_alist2[NN];
__device__ int g_nact[2];
__device__ unsigned g_prefix;

// weight offsets inside g_wt (all stored [N rows, K cols] row-major)
#define WO_EMB  0        // 256x128
#define WO_ENC0 32768    // 256x256
#define WO_ENC1 98304
#define WO_BOT  163840
#define WO_DEC0 229376
#define WO_DEC1 294912   // 128x256

__device__ __forceinline__ unsigned f2k(float f) {
    unsigned u = __float_as_uint(f);
    return (u & 0x80000000u) ? ~u : (u | 0x80000000u);
}

// ---------------- prep: zero counters + transpose all weights --------------
__global__ void prep_kernel(const float* __restrict__ We, const float* __restrict__ W0,
                            const float* __restrict__ W1, const float* __restrict__ Wb,
                            const float* __restrict__ Wd0, const float* __restrict__ Wd1) {
    int i = blockIdx.x * blockDim.x + threadIdx.x;
    if (i < NN) {
        g_rowoff[i] = 0; g_degout[i] = 0;
        g_degO1[i] = 0; g_degI1[i] = 0;
        g_degO2[i] = 0; g_degI2[i] = 0;
    }
    if (i == 0) { g_nact[0] = 0; g_nact[1] = 0; }
    if (i < 32768) {                       // embed: K=128,N=256
        int k = i >> 8, n = i & 255;
        g_wt[WO_EMB + n * 128 + k] = We[i];
    } else if (i < 98304) {                // enc0
        int j = i - 32768; int k = j >> 8, n = j & 255;
        g_wt[WO_ENC0 + n * 256 + k] = W0[j];
    } else if (i < 163840) {               // enc1
        int j = i - 98304; int k = j >> 8, n = j & 255;
        g_wt[WO_ENC1 + n * 256 + k] = W1[j];
    } else if (i < 229376) {               // bot
        int j = i - 163840; int k = j >> 8, n = j & 255;
        g_wt[WO_BOT + n * 256 + k] = Wb[j];
    } else if (i < 294912) {               // dec0
        int j = i - 229376; int k = j >> 8, n = j & 255;
        g_wt[WO_DEC0 + n * 256 + k] = Wd0[j];
    } else if (i < 327680) {               // dec1: K=256,N=128
        int j = i - 294912; int k = j >> 7, n = j & 127;
        g_wt[WO_DEC1 + n * 256 + k] = Wd1[j];
    }
}

// ---------------- CSR build ----------------
__global__ void hist_kernel(const int* __restrict__ src, const int* __restrict__ dst) {
    int e = blockIdx.x * blockDim.x + threadIdx.x;
    if (e < NE) {
        atomicAdd(&g_rowoff[dst[e]], 1);
        atomicAdd(&g_degout[src[e]], 1);
    }
}
__global__ void scan_kernel() {
    __shared__ int sh[1024];
    int tid = threadIdx.x;
    int carry = 0;
    for (int base = 0; base < NN; base += 1024) {
        int i = base + tid;
        int v = (i < NN) ? g_rowoff[i] : 0;
        int x = v;
        for (int off = 1; off < 1024; off <<= 1) {
            sh[tid] = x; __syncthreads();
            if (tid >= off) x += sh[tid - off];
            __syncthreads();
        }
        if (i < NN) { int rs = carry + x - v; g_rowstart[i] = rs; g_rowoff[i] = rs; }
        sh[tid] = x; __syncthreads();
        carry += sh[1023];
        __syncthreads();
    }
    if (tid == 0) g_rowstart[NN] = carry;
}
__global__ void scatter_kernel(const int* __restrict__ src, const int* __restrict__ dst) {
    int e = blockIdx.x * blockDim.x + threadIdx.x;
    if (e < NE) {
        int pos = atomicAdd(&g_rowoff[dst[e]], 1);
        g_csrsrc[pos] = src[e];
    }
}

// ---------------- unified CSR aggregation ----------------
// out[node] = (sum_src x[src]*scale(src)) * div(node) (+bias)
// scale: smul array | inline rsqrt(degsrc) | 1 ; div: divv array | inline rsqrt(deg_in)
__global__ void agg_kernel(const float* __restrict__ x, const float* __restrict__ smul,
                           const int* __restrict__ degsrc, const float* __restrict__ divv,
                           const int* __restrict__ alist, const float* __restrict__ bias,
                           float* __restrict__ out, int F) {
    int node = alist ? alist[blockIdx.x] : blockIdx.x;
    int f = threadIdx.x;
    int s = g_rowstart[node], e = g_rowstart[node + 1];
    __shared__ int sidx[64];
    __shared__ float sval[64];
    float acc = 0.f;
    for (int b = s; b < e; b += 64) {
        int nn = min(64, e - b);
        __syncthreads();
        if (f < nn) {
            int si = g_csrsrc[b + f];
            sidx[f] = si;
            float sc;
            if (smul) sc = smul[si];
            else if (degsrc) sc = rsqrtf((float)max(degsrc[si], 1));
            else sc = 1.f;
            sval[f] = sc;
        }
        __syncthreads();
        int k = 0;
        for (; k + 2 <= nn; k += 2) {
            float sc0 = sval[k], sc1 = sval[k + 1];
            float v0 = 0.f, v1 = 0.f;
            if (sc0 != 0.f) v0 = x[(size_t)sidx[k] * F + f];
            if (sc1 != 0.f) v1 = x[(size_t)sidx[k + 1] * F + f];
            acc = fmaf(v0, sc0, fmaf(v1, sc1, acc));
        }
        if (k < nn) {
            float sc = sval[k];
            if (sc != 0.f) acc = fmaf(x[(size_t)sidx[k] * F + f], sc, acc);
        }
    }
    float dv = divv ? divv[node] : rsqrtf((float)max(e - s, 1));
    float v = acc * dv;
    if (bias) v += bias[f];
    out[(size_t)node * F + f] = v;
}

// ---------------- HMMA fp16-split GEMM (split on load) ----------------
// C[rows,N] = act( A[rows,K] @ Bt[N,K]^T + bias ) * rsqrt(degrm) ; rows via alist
#define SMS 72
#define GEMM_SMEM (4 * 128 * SMS * 2)

#define MMA168(d, a, b) \
    asm volatile( \
        "mma.sync.aligned.m16n8k16.row.col.f32.f16.f16.f32 " \
        "{%0,%1,%2,%3}, {%4,%5,%6,%7}, {%8,%9}, {%0,%1,%2,%3};" \
        : "+f"((d)[0]), "+f"((d)[1]), "+f"((d)[2]), "+f"((d)[3]) \
        : "r"((a)[0]), "r"((a)[1]), "r"((a)[2]), "r"((a)[3]), \
          "r"((b)[0]), "r"((b)[1]))

__device__ __forceinline__ void split4(float4 v, __half2* ph, __half2* pl) {
    __half h0 = __float2half_rn(v.x), h1 = __float2half_rn(v.y);
    __half h2 = __float2half_rn(v.z), h3 = __float2half_rn(v.w);
    __half l0 = __float2half_rn(v.x - __half2float(h0));
    __half l1 = __float2half_rn(v.y - __half2float(h1));
    __half l2 = __float2half_rn(v.z - __half2float(h2));
    __half l3 = __float2half_rn(v.w - __half2float(h3));
    ph[0] = __halves2half2(h0, h1); ph[1] = __halves2half2(h2, h3);
    pl[0] = __halves2half2(l0, l1); pl[1] = __halves2half2(l2, l3);
}

__global__ void __launch_bounds__(256, 2)
gemm_kernel(const float* __restrict__ A, const float* __restrict__ Bt, float* __restrict__ C,
            int M, int K, int N, const int* __restrict__ alist,
            const float* __restrict__ bias, const int* __restrict__ degrm, int act) {
    extern __shared__ __half sm[];
    __half* sAh = sm;
    __half* sAl = sAh + 128 * SMS;
    __half* sBh = sAl + 128 * SMS;
    __half* sBl = sBh + 128 * SMS;
    int t = threadIdx.x;
    int m0 = blockIdx.y * 128, n0 = blockIdx.x * 128;
    int w = t >> 5, lane = t & 31;
    int g = lane >> 2, tig = lane & 3;
    int wm = (w & 1) * 64, wn = (w >> 1) * 32;

    float acc[4][4][4];
#pragma unroll
    for (int i = 0; i < 4; i++)
#pragma unroll
        for (int j = 0; j < 4; j++)
#pragma unroll
            for (int k = 0; k < 4; k++) acc[i][j][k] = 0.f;

    for (int kc = 0; kc < K; kc += 64) {
        for (int idx = t; idx < 2048; idx += 256) {
            int r = idx >> 4, c = idx & 15;
            int lr = m0 + r;
            float4 va = make_float4(0.f, 0.f, 0.f, 0.f);
            if (lr < M) {
                int gr = alist ? alist[lr] : lr;
                va = *(const float4*)(A + (size_t)gr * K + kc + c * 4);
            }
            split4(va, (__half2*)(sAh + r * SMS + c * 4), (__half2*)(sAl + r * SMS + c * 4));
            float4 vb = *(const float4*)(Bt + (size_t)(n0 + r) * K + kc + c * 4);
            split4(vb, (__half2*)(sBh + r * SMS + c * 4), (__half2*)(sBl + r * SMS + c * 4));
        }
        __syncthreads();
#pragma unroll
        for (int ks = 0; ks < 4; ks++) {
            int kb = ks * 16 + tig * 2;
            uint32_t ar[4][4], br[4][2], br2[4][2];
#pragma unroll
            for (int mi = 0; mi < 4; mi++) {
                int r = wm + mi * 16 + g;
                ar[mi][0] = *(const uint32_t*)(sAh + r * SMS + kb);
                ar[mi][1] = *(const uint32_t*)(sAh + (r + 8) * SMS + kb);
                ar[mi][2] = *(const uint32_t*)(sAh + r * SMS + kb + 8);
                ar[mi][3] = *(const uint32_t*)(sAh + (r + 8) * SMS + kb + 8);
            }
#pragma unroll
            for (int ni = 0; ni < 4; ni++) {
                int r = wn + ni * 8 + g;
                br[ni][0]  = *(const uint32_t*)(sBh + r * SMS + kb);
                br[ni][1]  = *(const uint32_t*)(sBh + r * SMS + kb + 8);
                br2[ni][0] = *(const uint32_t*)(sBl + r * SMS + kb);
                br2[ni][1] = *(const uint32_t*)(sBl + r * SMS + kb + 8);
            }
#pragma unroll
            for (int mi = 0; mi < 4; mi++)
#pragma unroll
                for (int ni = 0; ni < 4; ni++) {
                    MMA168(acc[mi][ni], ar[mi], br[ni]);
                    MMA168(acc[mi][ni], ar[mi], br2[ni]);
                }
#pragma unroll
            for (int mi = 0; mi < 4; mi++) {
                int r = wm + mi * 16 + g;
                ar[mi][0] = *(const uint32_t*)(sAl + r * SMS + kb);
                ar[mi][1] = *(const uint32_t*)(sAl + (r + 8) * SMS + kb);
                ar[mi][2] = *(const uint32_t*)(sAl + r * SMS + kb + 8);
                ar[mi][3] = *(const uint32_t*)(sAl + (r + 8) * SMS + kb + 8);
            }
#pragma unroll
            for (int mi = 0; mi < 4; mi++)
#pragma unroll
                for (int ni = 0; ni < 4; ni++)
                    MMA168(acc[mi][ni], ar[mi], br[ni]);
        }
        __syncthreads();
    }

#pragma unroll
    for (int mi = 0; mi < 4; mi++) {
#pragma unroll
        for (int half8 = 0; half8 < 2; half8++) {
            int lrow = m0 + wm + mi * 16 + g + half8 * 8;
            if (lrow >= M) continue;
            int grow = alist ? alist[lrow] : lrow;
            float rm = degrm ? rsqrtf((float)max(degrm[grow], 1)) : 1.f;
#pragma unroll
            for (int ni = 0; ni < 4; ni++) {
                int col = n0 + wn + ni * 8 + tig * 2;
                float v0 = acc[mi][ni][half8 * 2 + 0];
                float v1 = acc[mi][ni][half8 * 2 + 1];
                if (bias) { v0 += bias[col]; v1 += bias[col + 1]; }
                if (act) { v0 = fmaxf(v0, 0.f); v1 = fmaxf(v1, 0.f); }
                v0 *= rm; v1 *= rm;
                *(float2*)(C + (size_t)grow * N + col) = make_float2(v0, v1);
            }
        }
    }
}

// ---------------- pooling: scores, top-k, masks ----------------
__global__ void scores_kernel(const float* __restrict__ h, const float* __restrict__ Wp,
                              const float* __restrict__ bp, const float* __restrict__ msk) {
    int warp = (blockIdx.x * blockDim.x + threadIdx.x) >> 5;
    int lane = threadIdx.x & 31;
    if (warp >= NN) return;
    const float* hr = h + (size_t)warp * FH;
    float z = 0.f;
#pragma unroll
    for (int j = 0; j < 8; j++) z = fmaf(hr[lane + 32 * j], Wp[lane + 32 * j], z);
#pragma unroll
    for (int off = 16; off; off >>= 1) z += __shfl_xor_sync(0xFFFFFFFFu, z, off);
    if (lane == 0) {
        z += bp[0];
        float s = 1.f / (1.f + expf(-z));
        g_scores[warp] = s;
        float kin = (msk && msk[warp] == 0.f) ? -1e9f : s;
        g_keys[warp] = f2k(kin);
    }
}

// single-block exact top-K radix select (warp-aggregated histogram)
__global__ void topk_kernel(int K, int lvl) {
    __shared__ int hist[256];
    __shared__ unsigned s_pref;
    __shared__ int s_kr;
    int tid = threadIdx.x;
    if (tid == 0) { s_pref = 0u; s_kr = K; }
    const int NPAD = ((NN + 1023) / 1024) * 1024;
    for (int shift = 24; shift >= 0; shift -= 8) {
        if (tid < 256) hist[tid] = 0;
        __syncthreads();
        unsigned pref = s_pref;
        for (int i = tid; i < NPAD; i += 1024) {
            unsigned bucket = 0xFFFFFFFFu;
            if (i < NN) {
                unsigned k = g_keys[i];
                bool ok = (shift == 24) || ((k >> (shift + 8)) == (pref >> (shift + 8)));
                if (ok) bucket = (k >> shift) & 255u;
            }
            unsigned peers = __match_any_sync(0xFFFFFFFFu, bucket);
            if (bucket != 0xFFFFFFFFu) {
                int leader = __ffs(peers) - 1;
                if ((tid & 31) == leader) atomicAdd(&hist[bucket], __popc(peers));
            }
        }
        __syncthreads();
        if (tid == 0) {
            int kr = s_kr;
            for (int b = 255; b >= 0; b--) {
                int c = hist[b];
                if (c >= kr) { s_pref = pref | (((unsigned)b) << shift); break; }
                kr -= c;
            }
            s_kr = kr;
        }
        __syncthreads();
    }
    if (tid == 0) { g_prefix = s_pref; g_nact[lvl] = 0; }
}

__global__ void buildact_kernel(int* __restrict__ alist, int lvl) {
    int i = blockIdx.x * blockDim.x + threadIdx.x;
    if (i >= NN) return;
    if (g_keys[i] >= g_prefix) {
        int p = atomicAdd(&g_nact[lvl], 1);
        alist[p] = i;
    }
}

__global__ void degm_kernel(const int* __restrict__ src, const int* __restrict__ dst,
                            int* __restrict__ degO, int* __restrict__ degI) {
    int e = blockIdx.x * blockDim.x + threadIdx.x;
    if (e >= NE) return;
    int s = src[e], d = dst[e];
    if (g_keys[s] >= g_prefix && g_keys[d] >= g_prefix) {
        atomicAdd(&degO[s], 1);
        atomicAdd(&degI[d], 1);
    }
}

__global__ void fin_kernel(const int* __restrict__ degO, const int* __restrict__ degI,
                           float* __restrict__ comb, float* __restrict__ dov,
                           float* __restrict__ divv) {
    int i = blockIdx.x * blockDim.x + threadIdx.x;
    if (i >= NN) return;
    float mo = rsqrtf((float)max(degO[i], 1));
    bool a = g_keys[i] >= g_prefix;
    comb[i] = a ? g_scores[i] * mo : 0.f;
    dov[i] = a ? mo : 0.f;
    divv[i] = rsqrtf((float)max(degI[i], 1));
}

__global__ void preadd_kernel(const float* __restrict__ a, const float* __restrict__ b,
                              float* __restrict__ o) {
    int idx = blockIdx.x * blockDim.x + threadIdx.x;
    if (idx >= NN * (FH / 4)) return;
    float4 va = ((const float4*)a)[idx];
    float4 vb = ((const float4*)b)[idx];
    va.x += vb.x; va.y += vb.y; va.z += vb.z; va.w += vb.w;
    ((float4*)o)[idx] = va;
}

// ---------------- host orchestration ----------------
static inline void* sym(const void* s) {
    void* p = nullptr;
    cudaGetSymbolAddress(&p, (const void*)s);
    return p;
}

extern "C" void kernel_launch(void* const* d_in, const int* in_sizes, int n_in,
                              void* d_out, int out_size) {
    const float* features = (const float*)d_in[0];
    const int* src = (const int*)d_in[1];
    const int* dst = (const int*)d_in[2];
    const float* W_embed = (const float*)d_in[3];
    const float* b_embed = (const float*)d_in[4];
    const float* W_enc0 = (const float*)d_in[5];
    const float* b_enc0 = (const float*)d_in[6];
    const float* W_enc1 = (const float*)d_in[7];
    const float* b_enc1 = (const float*)d_in[8];
    const float* W_p0 = (const float*)d_in[9];
    const float* b_p0 = (const float*)d_in[10];
    const float* W_p1 = (const float*)d_in[11];
    const float* b_p1 = (const float*)d_in[12];
    const float* W_bot = (const float*)d_in[13];
    const float* b_bot = (const float*)d_in[14];
    const float* W_dec0 = (const float*)d_in[15];
    const float* b_dec0 = (const float*)d_in[16];
    const float* W_dec1 = (const float*)d_in[17];
    const float* b_dec1 = (const float*)d_in[18];
    float* out = (float*)d_out;

    float* p_xa   = (float*)sym(g_xa);
    float* p_h    = (float*)sym(g_h);
    float* p_hid0 = (float*)sym(g_hid0);
    float* p_hid1 = (float*)sym(g_hid1);
    float* p_hbot = (float*)sym(g_hbot);
    float* p_h4   = (float*)sym(g_h4);
    float* p_wt   = (float*)sym(g_wt);
    int* p_degout = (int*)sym(g_degout);
    int* p_degO1  = (int*)sym(g_degO1);
    int* p_degI1  = (int*)sym(g_degI1);
    int* p_degO2  = (int*)sym(g_degO2);
    int* p_degI2  = (int*)sym(g_degI2);
    float* p_comb1 = (float*)sym(g_comb1);
    float* p_dov1  = (float*)sym(g_dov1);
    float* p_div1  = (float*)sym(g_div1);
    float* p_comb2 = (float*)sym(g_comb2);
    float* p_dov2  = (float*)sym(g_dov2);
    float* p_div2  = (float*)sym(g_div2);
    int* p_al1 = (int*)sym(g_alist1);
    int* p_al2 = (int*)sym(g_alist2);

    cudaFuncSetAttribute(gemm_kernel, cudaFuncAttributeMaxDynamicSharedMemorySize, GEMM_SMEM);

    const int TB = 256;
    const int NB_N = (NN + TB - 1) / TB;
    const int NB_E = (NE + TB - 1) / TB;
    dim3 gFull256(2, (NN + 127) / 128);
    dim3 gFull128(1, (NN + 127) / 128);
    dim3 gK1(2, (K1 + 127) / 128);
    dim3 gK2(2, (K2 + 127) / 128);

    // 1-4: prep + CSR build
    prep_kernel<<<(327680 + TB - 1) / TB, TB>>>(W_embed, W_enc0, W_enc1, W_bot, W_dec0, W_dec1);
    hist_kernel<<<NB_E, TB>>>(src, dst);
    scan_kernel<<<1, 1024>>>();
    scatter_kernel<<<NB_E, TB>>>(src, dst);

    // L0: agg(features * dovF) * divF -> xa ; GEMM 128->256 -> h
    agg_kernel<<<NN, FI>>>(features, nullptr, p_degout, nullptr, nullptr, nullptr, p_xa, FI);
    gemm_kernel<<<gFull256, 256, GEMM_SMEM>>>(p_xa, p_wt + WO_EMB, p_h, NN, FI, FH,
                                              nullptr, b_embed, nullptr, 1);

    // L1: full graph -> hid0
    agg_kernel<<<NN, FH>>>(p_h, nullptr, p_degout, nullptr, nullptr, nullptr, p_xa, FH);
    gemm_kernel<<<gFull256, 256, GEMM_SMEM>>>(p_xa, p_wt + WO_ENC0, p_hid0, NN, FH, FH,
                                              nullptr, b_enc0, nullptr, 1);

    // pool0
    scores_kernel<<<(NN + 7) / 8, TB>>>(p_hid0, W_p0, b_p0, nullptr);
    topk_kernel<<<1, 1024>>>(K1, 0);
    buildact_kernel<<<NB_N, TB>>>(p_al1, 0);
    degm_kernel<<<NB_E, TB>>>(src, dst, p_degO1, p_degI1);
    fin_kernel<<<NB_N, TB>>>(p_degO1, p_degI1, p_comb1, p_dov1, p_div1);

    // L2: compacted M=K1 -> hid1 (inactive rows stay 0)
    agg_kernel<<<K1, FH>>>(p_hid0, p_comb1, nullptr, p_div1, p_al1, nullptr, p_xa, FH);
    gemm_kernel<<<gK1, 256, GEMM_SMEM>>>(p_xa, p_wt + WO_ENC1, p_hid1, K1, FH, FH,
                                         p_al1, b_enc1, nullptr, 1);

    // pool1 (mask = dov1: nonzero iff node active in level 1)
    scores_kernel<<<(NN + 7) / 8, TB>>>(p_hid1, W_p1, b_p1, p_dov1);
    topk_kernel<<<1, 1024>>>(K2, 1);
    buildact_kernel<<<NB_N, TB>>>(p_al2, 1);
    degm_kernel<<<NB_E, TB>>>(src, dst, p_degO2, p_degI2);
    fin_kernel<<<NB_N, TB>>>(p_degO2, p_degI2, p_comb2, p_dov2, p_div2);

    // L3: compacted M=K2 -> hbot
    agg_kernel<<<K2, FH>>>(p_hid1, p_comb2, nullptr, p_div2, p_al2, nullptr, p_xa, FH);
    gemm_kernel<<<gK2, 256, GEMM_SMEM>>>(p_xa, p_wt + WO_BOT, p_hbot, K2, FH, FH,
                                         p_al2, b_bot, nullptr, 1);

    // L4: h = hbot + hid1 (skip); agg over m1 subgraph (src scale dov1); M=K1 -> h4
    preadd_kernel<<<(NN * (FH / 4) + TB - 1) / TB, TB>>>(p_hbot, p_hid1, p_h);
    agg_kernel<<<K1, FH>>>(p_h, p_dov1, nullptr, p_div1, p_al1, nullptr, p_xa, FH);
    gemm_kernel<<<gK1, 256, GEMM_SMEM>>>(p_xa, p_wt + WO_DEC0, p_h4, K1, FH, FH,
                                         p_al1, b_dec0, nullptr, 1);

    // L5: h = h4 + hid0; GEMM first (256->128, rowmul=dovF inline), then agg + bias -> out
    preadd_kernel<<<(NN * (FH / 4) + TB - 1) / TB, TB>>>(p_h4, p_hid0, p_h);
    gemm_kernel<<<gFull128, 256, GEMM_SMEM>>>(p_h, p_wt + WO_DEC1, p_xa, NN, FH, FI,
                                              nullptr, nullptr, p_degout, 0);
    agg_kernel<<<NN, FI>>>(p_xa, nullptr, nullptr, nullptr, nullptr, b_dec1, out, FI);
}

// round 5
// speedup vs baseline: 2.9904x; 1.4737x over previous
#include <cuda_runtime.h>
#include <cuda_fp16.h>
#include <math.h>
#include <stdint.h>

#define NN 50000
#define NE 800000
#define FI 128
#define FH 256
#define K1 25000
#define K2 12500
#define NSCAN 49  // ceil(NN/1024)

// ---------------- scratch (device globals; zero-init, allocation-free) -----
__device__ __align__(16) float g_xa[NN * FH];    // L5 gemm out
__device__ __align__(16) float g_h[NN * FH];     // L0 gemm out
__device__ __align__(16) float g_hid0[NN * FH];  // L1 out (full)
__device__ __align__(16) float g_hid1[NN * FH];  // L2 out (scattered; else 0)
__device__ __align__(16) float g_hbot[NN * FH];  // L3 out (scattered; else 0)
__device__ __align__(16) float g_h4[NN * FH];    // L4 out (scattered; else 0)
__device__ __align__(16) __half g_xh[NN * FH];   // gemm A hi
__device__ __align__(16) __half g_xl[NN * FH];   // gemm A lo
__device__ __align__(16) __half g_wth[327680];   // weights hi (transposed)
__device__ __align__(16) __half g_wtl[327680];   // weights lo
__device__ int g_degout[NN];
__device__ int g_degO1[NN], g_degI1[NN], g_degO2[NN], g_degI2[NN];
__device__ float g_comb1[NN], g_dov1[NN], g_div1[NN];
__device__ float g_comb2[NN], g_dov2[NN], g_div2[NN];
__device__ float g_scores[NN];
__device__ unsigned g_keys[NN];
__device__ int g_rowstart[NN + 1];
__device__ int g_rowoff[NN];
__device__ int g_csrsrc[NE];
__device__ int g_alist1[NN], g_alist2[NN];
__device__ int g_nact[2];
__device__ unsigned g_prefix;
__device__ int g_bsum[64], g_boff[64];

#define WO_EMB  0
#define WO_ENC0 32768
#define WO_ENC1 98304
#define WO_BOT  163840
#define WO_DEC0 229376
#define WO_DEC1 294912

__device__ __forceinline__ unsigned f2k(float f) {
    unsigned u = __float_as_uint(f);
    return (u & 0x80000000u) ? ~u : (u | 0x80000000u);
}
__device__ __forceinline__ void split4(float4 v, __half2* ph, __half2* pl) {
    __half h0 = __float2half_rn(v.x), h1 = __float2half_rn(v.y);
    __half h2 = __float2half_rn(v.z), h3 = __float2half_rn(v.w);
    __half l0 = __float2half_rn(v.x - __half2float(h0));
    __half l1 = __float2half_rn(v.y - __half2float(h1));
    __half l2 = __float2half_rn(v.z - __half2float(h2));
    __half l3 = __float2half_rn(v.w - __half2float(h3));
    ph[0] = __halves2half2(h0, h1); ph[1] = __halves2half2(h2, h3);
    pl[0] = __halves2half2(l0, l1); pl[1] = __halves2half2(l2, l3);
}

// ---------------- prep: zero counters + transpose+split all weights --------
__global__ void prep_kernel(const float* __restrict__ We, const float* __restrict__ W0,
                            const float* __restrict__ W1, const float* __restrict__ Wb,
                            const float* __restrict__ Wd0, const float* __restrict__ Wd1) {
    int i = blockIdx.x * blockDim.x + threadIdx.x;
    if (i < NN) {
        g_rowoff[i] = 0; g_degout[i] = 0;
        g_degO1[i] = 0; g_degI1[i] = 0;
        g_degO2[i] = 0; g_degI2[i] = 0;
    }
    if (i == 0) { g_nact[0] = 0; g_nact[1] = 0; g_rowstart[NN] = NE; }
    float w; int o;
    if (i < 32768) {                       // embed: K=128,N=256
        int k = i >> 8, n = i & 255;
        w = We[i]; o = WO_EMB + n * 128 + k;
    } else if (i < 98304) {
        int j = i - 32768; int k = j >> 8, n = j & 255;
        w = W0[j]; o = WO_ENC0 + n * 256 + k;
    } else if (i < 163840) {
        int j = i - 98304; int k = j >> 8, n = j & 255;
        w = W1[j]; o = WO_ENC1 + n * 256 + k;
    } else if (i < 229376) {
        int j = i - 163840; int k = j >> 8, n = j & 255;
        w = Wb[j]; o = WO_BOT + n * 256 + k;
    } else if (i < 294912) {
        int j = i - 229376; int k = j >> 8, n = j & 255;
        w = Wd0[j]; o = WO_DEC0 + n * 256 + k;
    } else if (i < 327680) {               // dec1: K=256,N=128
        int j = i - 294912; int k = j >> 7, n = j & 127;
        w = Wd1[j]; o = WO_DEC1 + n * 256 + k;
    } else return;
    __half h = __float2half_rn(w);
    g_wth[o] = h;
    g_wtl[o] = __float2half_rn(w - __half2float(h));
}

// ---------------- CSR build ----------------
__global__ void hist_kernel(const int* __restrict__ src, const int* __restrict__ dst) {
    int e = blockIdx.x * blockDim.x + threadIdx.x;
    if (e < NE) {
        atomicAdd(&g_rowoff[dst[e]], 1);
        atomicAdd(&g_degout[src[e]], 1);
    }
}
__global__ void scan1_kernel() {
    int b = blockIdx.x, t = threadIdx.x;
    int i = b * 1024 + t;
    int v = (i < NN) ? g_rowoff[i] : 0;
    int lane = t & 31, wid = t >> 5;
    int x = v;
#pragma unroll
    for (int off = 1; off < 32; off <<= 1) {
        int y = __shfl_up_sync(0xFFFFFFFFu, x, off);
        if (lane >= off) x += y;
    }
    __shared__ int ws[32];
    if (lane == 31) ws[wid] = x;
    __syncthreads();
    if (wid == 0) {
        int y = ws[lane];
#pragma unroll
        for (int off = 1; off < 32; off <<= 1) {
            int z = __shfl_up_sync(0xFFFFFFFFu, y, off);
            if (lane >= off) y += z;
        }
        ws[lane] = y;
    }
    __syncthreads();
    int base = wid ? ws[wid - 1] : 0;
    if (i < NN) g_rowstart[i] = base + x - v;
    if (t == 1023) g_bsum[b] = base + x;
}
__global__ void scan2_kernel() {
    if (threadIdx.x == 0) {
        int run = 0;
        for (int b = 0; b < NSCAN; b++) { g_boff[b] = run; run += g_bsum[b]; }
    }
}
__global__ void scan3_kernel() {
    int i = blockIdx.x * blockDim.x + threadIdx.x;
    if (i < NN) {
        int rs = g_rowstart[i] + g_boff[i >> 10];
        g_rowstart[i] = rs;
        g_rowoff[i] = rs;
    }
}
__global__ void scatter_kernel(const int* __restrict__ src, const int* __restrict__ dst) {
    int e = blockIdx.x * blockDim.x + threadIdx.x;
    if (e < NE) {
        int pos = atomicAdd(&g_rowoff[dst[e]], 1);
        g_csrsrc[pos] = src[e];
    }
}

// ---------------- CSR aggregation (float4, fp16-split output) ----------------
// wrow = alist?blockIdx.x:node (compact); out = (sum_src (x+x2)[src]*sc(src)) * div(node)
__global__ void agg_half_kernel(const float* __restrict__ x, const float* __restrict__ x2,
                                const float* __restrict__ smul, const int* __restrict__ degsrc,
                                const float* __restrict__ divv, const int* __restrict__ alist,
                                __half* __restrict__ oh, __half* __restrict__ ol, int F) {
    int node = alist ? alist[blockIdx.x] : blockIdx.x;
    int t = threadIdx.x;            // 0..F/4-1
    int f4 = F >> 2;
    int s = g_rowstart[node], e = g_rowstart[node + 1];
    __shared__ int sidx[32];
    __shared__ float sval[32];
    float4 acc = make_float4(0.f, 0.f, 0.f, 0.f);
    for (int b = s; b < e; b += 32) {
        int nn = min(32, e - b);
        __syncthreads();
        if (t < nn) {
            int si = g_csrsrc[b + t];
            sidx[t] = si;
            float sc;
            if (smul) sc = smul[si];
            else if (degsrc) sc = rsqrtf((float)max(degsrc[si], 1));
            else sc = 1.f;
            sval[t] = sc;
        }
        __syncthreads();
        for (int k = 0; k < nn; k++) {
            float sc = sval[k];
            if (sc != 0.f) {
                size_t o = (size_t)sidx[k] * f4 + t;
                float4 v = ((const float4*)x)[o];
                if (x2) {
                    float4 w = ((const float4*)x2)[o];
                    v.x += w.x; v.y += w.y; v.z += w.z; v.w += w.w;
                }
                acc.x = fmaf(v.x, sc, acc.x); acc.y = fmaf(v.y, sc, acc.y);
                acc.z = fmaf(v.z, sc, acc.z); acc.w = fmaf(v.w, sc, acc.w);
            }
        }
    }
    float dv = divv ? divv[node] : rsqrtf((float)max(e - s, 1));
    acc.x *= dv; acc.y *= dv; acc.z *= dv; acc.w *= dv;
    int wrow = alist ? blockIdx.x : node;
    size_t o = (size_t)wrow * F + t * 4;
    split4(acc, (__half2*)(oh + o), (__half2*)(ol + o));
}

// final-layer variant: fp32 out + bias, unit scale, inline divs
__global__ void agg_out_kernel(const float* __restrict__ x, const float* __restrict__ bias,
                               float* __restrict__ out, int F) {
    int node = blockIdx.x;
    int t = threadIdx.x;
    int f4 = F >> 2;
    int s = g_rowstart[node], e = g_rowstart[node + 1];
    __shared__ int sidx[32];
    float4 acc = make_float4(0.f, 0.f, 0.f, 0.f);
    for (int b = s; b < e; b += 32) {
        int nn = min(32, e - b);
        __syncthreads();
        if (t < nn) sidx[t] = g_csrsrc[b + t];
        __syncthreads();
        for (int k = 0; k < nn; k++) {
            float4 v = ((const float4*)x)[(size_t)sidx[k] * f4 + t];
            acc.x += v.x; acc.y += v.y; acc.z += v.z; acc.w += v.w;
        }
    }
    float dv = rsqrtf((float)max(e - s, 1));
    float4 bb = ((const float4*)bias)[t];
    acc.x = fmaf(acc.x, dv, bb.x); acc.y = fmaf(acc.y, dv, bb.y);
    acc.z = fmaf(acc.z, dv, bb.z); acc.w = fmaf(acc.w, dv, bb.w);
    ((float4*)out)[(size_t)node * f4 + t] = acc;
}

// ---------------- HMMA fp16-split GEMM ----------------
#define SMS 72
#define GEMM_SMEM (4 * 128 * SMS * 2)

#define MMA168(d, a, b) \
    asm volatile( \
        "mma.sync.aligned.m16n8k16.row.col.f32.f16.f16.f32 " \
        "{%0,%1,%2,%3}, {%4,%5,%6,%7}, {%8,%9}, {%0,%1,%2,%3};" \
        : "+f"((d)[0]), "+f"((d)[1]), "+f"((d)[2]), "+f"((d)[3]) \
        : "r"((a)[0]), "r"((a)[1]), "r"((a)[2]), "r"((a)[3]), \
          "r"((b)[0]), "r"((b)[1]))

// AHALF=1: A given as pre-split halves (Ah/Al). AHALF=0: A = A0 (+A1), split on load.
template <int AHALF>
__global__ void __launch_bounds__(256, 2)
gemm_kernel(const __half* __restrict__ Ah, const __half* __restrict__ Al,
            const float* __restrict__ A0, const float* __restrict__ A1,
            const __half* __restrict__ Bh, const __half* __restrict__ Bl,
            float* __restrict__ C, int M, int K, int N,
            const int* __restrict__ alist, const float* __restrict__ bias,
            const int* __restrict__ degrm, int act) {
    extern __shared__ __half sm[];
    __half* sAh = sm;
    __half* sAl = sAh + 128 * SMS;
    __half* sBh = sAl + 128 * SMS;
    __half* sBl = sBh + 128 * SMS;
    int t = threadIdx.x;
    int m0 = blockIdx.y * 128, n0 = blockIdx.x * 128;
    int w = t >> 5, lane = t & 31;
    int g = lane >> 2, tig = lane & 3;
    int wm = (w & 1) * 64, wn = (w >> 1) * 32;

    float acc[4][4][4];
#pragma unroll
    for (int i = 0; i < 4; i++)
#pragma unroll
        for (int j = 0; j < 4; j++)
#pragma unroll
            for (int k = 0; k < 4; k++) acc[i][j][k] = 0.f;

    for (int kc = 0; kc < K; kc += 64) {
        if (AHALF) {
            for (int idx = t; idx < 2048; idx += 256) {
                int arr = idx >> 10, j = idx & 1023, r = j >> 3, c = j & 7;
                const __half* srcp = arr ? Al : Ah;
                uint4 v = make_uint4(0, 0, 0, 0);
                if (m0 + r < M) v = *(const uint4*)(srcp + (size_t)(m0 + r) * K + kc + c * 8);
                *(uint4*)((arr ? sAl : sAh) + r * SMS + c * 8) = v;
            }
        } else {
            for (int idx = t; idx < 1024; idx += 256) {
                int r = idx >> 3, c = idx & 7;
                float4 f0 = make_float4(0.f, 0.f, 0.f, 0.f), f1 = f0;
                if (m0 + r < M) {
                    size_t o = (size_t)(m0 + r) * K + kc + c * 8;
                    f0 = *(const float4*)(A0 + o);
                    f1 = *(const float4*)(A0 + o + 4);
                    float4 q0 = *(const float4*)(A1 + o);
                    float4 q1 = *(const float4*)(A1 + o + 4);
                    f0.x += q0.x; f0.y += q0.y; f0.z += q0.z; f0.w += q0.w;
                    f1.x += q1.x; f1.y += q1.y; f1.z += q1.z; f1.w += q1.w;
                }
                split4(f0, (__half2*)(sAh + r * SMS + c * 8), (__half2*)(sAl + r * SMS + c * 8));
                split4(f1, (__half2*)(sAh + r * SMS + c * 8 + 4), (__half2*)(sAl + r * SMS + c * 8 + 4));
            }
        }
        for (int idx = t; idx < 2048; idx += 256) {
            int arr = idx >> 10, j = idx & 1023, r = j >> 3, c = j & 7;
            const __half* srcp = arr ? Bl : Bh;
            uint4 v = *(const uint4*)(srcp + (size_t)(n0 + r) * K + kc + c * 8);
            *(uint4*)((arr ? sBl : sBh) + r * SMS + c * 8) = v;
        }
        __syncthreads();
#pragma unroll
        for (int ks = 0; ks < 4; ks++) {
            int kb = ks * 16 + tig * 2;
            uint32_t ar[4][4], br[4][2], br2[4][2];
#pragma unroll
            for (int mi = 0; mi < 4; mi++) {
                int r = wm + mi * 16 + g;
                ar[mi][0] = *(const uint32_t*)(sAh + r * SMS + kb);
                ar[mi][1] = *(const uint32_t*)(sAh + (r + 8) * SMS + kb);
                ar[mi][2] = *(const uint32_t*)(sAh + r * SMS + kb + 8);
                ar[mi][3] = *(const uint32_t*)(sAh + (r + 8) * SMS + kb + 8);
            }
#pragma unroll
            for (int ni = 0; ni < 4; ni++) {
                int r = wn + ni * 8 + g;
                br[ni][0]  = *(const uint32_t*)(sBh + r * SMS + kb);
                br[ni][1]  = *(const uint32_t*)(sBh + r * SMS + kb + 8);
                br2[ni][0] = *(const uint32_t*)(sBl + r * SMS + kb);
                br2[ni][1] = *(const uint32_t*)(sBl + r * SMS + kb + 8);
            }
#pragma unroll
            for (int mi = 0; mi < 4; mi++)
#pragma unroll
                for (int ni = 0; ni < 4; ni++) {
                    MMA168(acc[mi][ni], ar[mi], br[ni]);
                    MMA168(acc[mi][ni], ar[mi], br2[ni]);
                }
#pragma unroll
            for (int mi = 0; mi < 4; mi++) {
                int r = wm + mi * 16 + g;
                ar[mi][0] = *(const uint32_t*)(sAl + r * SMS + kb);
                ar[mi][1] = *(const uint32_t*)(sAl + (r + 8) * SMS + kb);
                ar[mi][2] = *(const uint32_t*)(sAl + r * SMS + kb + 8);
                ar[mi][3] = *(const uint32_t*)(sAl + (r + 8) * SMS + kb + 8);
            }
#pragma unroll
            for (int mi = 0; mi < 4; mi++)
#pragma unroll
                for (int ni = 0; ni < 4; ni++)
                    MMA168(acc[mi][ni], ar[mi], br[ni]);
        }
        __syncthreads();
    }

#pragma unroll
    for (int mi = 0; mi < 4; mi++) {
#pragma unroll
        for (int half8 = 0; half8 < 2; half8++) {
            int lrow = m0 + wm + mi * 16 + g + half8 * 8;
            if (lrow >= M) continue;
            int grow = alist ? alist[lrow] : lrow;
            float rm = degrm ? rsqrtf((float)max(degrm[grow], 1)) : 1.f;
#pragma unroll
            for (int ni = 0; ni < 4; ni++) {
                int col = n0 + wn + ni * 8 + tig * 2;
                float v0 = acc[mi][ni][half8 * 2 + 0];
                float v1 = acc[mi][ni][half8 * 2 + 1];
                if (bias) { v0 += bias[col]; v1 += bias[col + 1]; }
                if (act) { v0 = fmaxf(v0, 0.f); v1 = fmaxf(v1, 0.f); }
                v0 *= rm; v1 *= rm;
                *(float2*)(C + (size_t)grow * N + col) = make_float2(v0, v1);
            }
        }
    }
}

// ---------------- pooling: scores, top-k, masks ----------------
__global__ void scores_kernel(const float* __restrict__ h, const float* __restrict__ Wp,
                              const float* __restrict__ bp, const float* __restrict__ msk) {
    int warp = (blockIdx.x * blockDim.x + threadIdx.x) >> 5;
    int lane = threadIdx.x & 31;
    if (warp >= NN) return;
    const float* hr = h + (size_t)warp * FH;
    float z = 0.f;
#pragma unroll
    for (int j = 0; j < 8; j++) z = fmaf(hr[lane + 32 * j], Wp[lane + 32 * j], z);
#pragma unroll
    for (int off = 16; off; off >>= 1) z += __shfl_xor_sync(0xFFFFFFFFu, z, off);
    if (lane == 0) {
        z += bp[0];
        float s = 1.f / (1.f + expf(-z));
        g_scores[warp] = s;
        float kin = (msk && msk[warp] == 0.f) ? -1e9f : s;
        g_keys[warp] = f2k(kin);
    }
}

__global__ void topk_kernel(int K, int lvl) {
    __shared__ int hist[256];
    __shared__ unsigned s_pref;
    __shared__ int s_kr;
    int tid = threadIdx.x;
    if (tid == 0) { s_pref = 0u; s_kr = K; }
    const int NPAD = ((NN + 1023) / 1024) * 1024;
    for (int shift = 24; shift >= 0; shift -= 8) {
        if (tid < 256) hist[tid] = 0;
        __syncthreads();
        unsigned pref = s_pref;
        for (int i = tid; i < NPAD; i += 1024) {
            unsigned bucket = 0xFFFFFFFFu;
            if (i < NN) {
                unsigned k = g_keys[i];
                bool ok = (shift == 24) || ((k >> (shift + 8)) == (pref >> (shift + 8)));
                if (ok) bucket = (k >> shift) & 255u;
            }
            unsigned peers = __match_any_sync(0xFFFFFFFFu, bucket);
            if (bucket != 0xFFFFFFFFu) {
                int leader = __ffs(peers) - 1;
                if ((tid & 31) == leader) atomicAdd(&hist[bucket], __popc(peers));
            }
        }
        __syncthreads();
        if (tid == 0) {
            int kr = s_kr;
            for (int b = 255; b >= 0; b--) {
                int c = hist[b];
                if (c >= kr) { s_pref = pref | (((unsigned)b) << shift); break; }
                kr -= c;
            }
            s_kr = kr;
        }
        __syncthreads();
    }
    if (tid == 0) { g_prefix = s_pref; g_nact[lvl] = 0; }
}

__global__ void buildact_kernel(int* __restrict__ alist, int lvl) {
    int i = blockIdx.x * blockDim.x + threadIdx.x;
    if (i >= NN) return;
    if (g_keys[i] >= g_prefix) {
        int p = atomicAdd(&g_nact[lvl], 1);
        alist[p] = i;
    }
}

__global__ void degm_kernel(const int* __restrict__ src, const int* __restrict__ dst,
                            int* __restrict__ degO, int* __restrict__ degI) {
    int e = blockIdx.x * blockDim.x + threadIdx.x;
    if (e >= NE) return;
    int s = src[e], d = dst[e];
    if (g_keys[s] >= g_prefix && g_keys[d] >= g_prefix) {
        atomicAdd(&degO[s], 1);
        atomicAdd(&degI[d], 1);
    }
}

__global__ void fin_kernel(const int* __restrict__ degO, const int* __restrict__ degI,
                           float* __restrict__ comb, float* __restrict__ dov,
                           float* __restrict__ divv) {
    int i = blockIdx.x * blockDim.x + threadIdx.x;
    if (i >= NN) return;
    float mo = rsqrtf((float)max(degO[i], 1));
    bool a = g_keys[i] >= g_prefix;
    comb[i] = a ? g_scores[i] * mo : 0.f;
    dov[i] = a ? mo : 0.f;
    divv[i] = rsqrtf((float)max(degI[i], 1));
}

// ---------------- host orchestration ----------------
static inline void* sym(const void* s) {
    void* p = nullptr;
    cudaGetSymbolAddress(&p, (const void*)s);
    return p;
}

extern "C" void kernel_launch(void* const* d_in, const int* in_sizes, int n_in,
                              void* d_out, int out_size) {
    const float* features = (const float*)d_in[0];
    const int* src = (const int*)d_in[1];
    const int* dst = (const int*)d_in[2];
    const float* W_embed = (const float*)d_in[3];
    const float* b_embed = (const float*)d_in[4];
    const float* W_enc0 = (const float*)d_in[5];
    const float* b_enc0 = (const float*)d_in[6];
    const float* W_enc1 = (const float*)d_in[7];
    const float* b_enc1 = (const float*)d_in[8];
    const float* W_p0 = (const float*)d_in[9];
    const float* b_p0 = (const float*)d_in[10];
    const float* W_p1 = (const float*)d_in[11];
    const float* b_p1 = (const float*)d_in[12];
    const float* W_bot = (const float*)d_in[13];
    const float* b_bot = (const float*)d_in[14];
    const float* W_dec0 = (const float*)d_in[15];
    const float* b_dec0 = (const float*)d_in[16];
    const float* W_dec1 = (const float*)d_in[17];
    const float* b_dec1 = (const float*)d_in[18];
    float* out = (float*)d_out;

    float* p_xa   = (float*)sym(g_xa);
    float* p_h    = (float*)sym(g_h);
    float* p_hid0 = (float*)sym(g_hid0);
    float* p_hid1 = (float*)sym(g_hid1);
    float* p_hbot = (float*)sym(g_hbot);
    float* p_h4   = (float*)sym(g_h4);
    __half* p_xh  = (__half*)sym(g_xh);
    __half* p_xl  = (__half*)sym(g_xl);
    __half* p_wth = (__half*)sym(g_wth);
    __half* p_wtl = (__half*)sym(g_wtl);
    int* p_degout = (int*)sym(g_degout);
    int* p_degO1  = (int*)sym(g_degO1);
    int* p_degI1  = (int*)sym(g_degI1);
    int* p_degO2  = (int*)sym(g_degO2);
    int* p_degI2  = (int*)sym(g_degI2);
    float* p_comb1 = (float*)sym(g_comb1);
    float* p_dov1  = (float*)sym(g_dov1);
    float* p_div1  = (float*)sym(g_div1);
    float* p_comb2 = (float*)sym(g_comb2);
    float* p_dov2  = (float*)sym(g_dov2);
    float* p_div2  = (float*)sym(g_div2);
    int* p_al1 = (int*)sym(g_alist1);
    int* p_al2 = (int*)sym(g_alist2);

    cudaFuncSetAttribute(gemm_kernel<1>, cudaFuncAttributeMaxDynamicSharedMemorySize, GEMM_SMEM);
    cudaFuncSetAttribute(gemm_kernel<0>, cudaFuncAttributeMaxDynamicSharedMemorySize, GEMM_SMEM);

    const int TB = 256;
    const int NB_N = (NN + TB - 1) / TB;
    const int NB_E = (NE + TB - 1) / TB;
    dim3 gFull256(2, (NN + 127) / 128);
    dim3 gFull128(1, (NN + 127) / 128);
    dim3 gK1(2, (K1 + 127) / 128);
    dim3 gK2(2, (K2 + 127) / 128);

    // prep + CSR build
    prep_kernel<<<(327680 + TB - 1) / TB, TB>>>(W_embed, W_enc0, W_enc1, W_bot, W_dec0, W_dec1);
    hist_kernel<<<NB_E, TB>>>(src, dst);
    scan1_kernel<<<NSCAN, 1024>>>();
    scan2_kernel<<<1, 32>>>();
    scan3_kernel<<<NB_N, TB>>>();
    scatter_kernel<<<NB_E, TB>>>(src, dst);

    // L0: agg(features) -> xh/xl ; GEMM 128->256 -> h
    agg_half_kernel<<<NN, FI / 4>>>(features, nullptr, nullptr, p_degout, nullptr, nullptr,
                                    p_xh, p_xl, FI);
    gemm_kernel<1><<<gFull256, 256, GEMM_SMEM>>>(p_xh, p_xl, nullptr, nullptr,
                                                 p_wth + WO_EMB, p_wtl + WO_EMB, p_h,
                                                 NN, FI, FH, nullptr, b_embed, nullptr, 1);

    // L1: full graph -> hid0
    agg_half_kernel<<<NN, FH / 4>>>(p_h, nullptr, nullptr, p_degout, nullptr, nullptr,
                                    p_xh, p_xl, FH);
    gemm_kernel<1><<<gFull256, 256, GEMM_SMEM>>>(p_xh, p_xl, nullptr, nullptr,
                                                 p_wth + WO_ENC0, p_wtl + WO_ENC0, p_hid0,
                                                 NN, FH, FH, nullptr, b_enc0, nullptr, 1);

    // pool0
    scores_kernel<<<(NN + 7) / 8, TB>>>(p_hid0, W_p0, b_p0, nullptr);
    topk_kernel<<<1, 1024>>>(K1, 0);
    buildact_kernel<<<NB_N, TB>>>(p_al1, 0);
    degm_kernel<<<NB_E, TB>>>(src, dst, p_degO1, p_degI1);
    fin_kernel<<<NB_N, TB>>>(p_degO1, p_degI1, p_comb1, p_dov1, p_div1);

    // L2: compact M=K1 -> hid1 (scatter)
    agg_half_kernel<<<K1, FH / 4>>>(p_hid0, nullptr, p_comb1, nullptr, p_div1, p_al1,
                                    p_xh, p_xl, FH);
    gemm_kernel<1><<<gK1, 256, GEMM_SMEM>>>(p_xh, p_xl, nullptr, nullptr,
                                            p_wth + WO_ENC1, p_wtl + WO_ENC1, p_hid1,
                                            K1, FH, FH, p_al1, b_enc1, nullptr, 1);

    // pool1
    scores_kernel<<<(NN + 7) / 8, TB>>>(p_hid1, W_p1, b_p1, p_dov1);
    topk_kernel<<<1, 1024>>>(K2, 1);
    buildact_kernel<<<NB_N, TB>>>(p_al2, 1);
    degm_kernel<<<NB_E, TB>>>(src, dst, p_degO2, p_degI2);
    fin_kernel<<<NB_N, TB>>>(p_degO2, p_degI2, p_comb2, p_dov2, p_div2);

    // L3: compact M=K2 -> hbot (scatter)
    agg_half_kernel<<<K2, FH / 4>>>(p_hid1, nullptr, p_comb2, nullptr, p_div2, p_al2,
                                    p_xh, p_xl, FH);
    gemm_kernel<1><<<gK2, 256, GEMM_SMEM>>>(p_xh, p_xl, nullptr, nullptr,
                                            p_wth + WO_BOT, p_wtl + WO_BOT, p_hbot,
                                            K2, FH, FH, p_al2, b_bot, nullptr, 1);

    // L4: agg((hbot+hid1)*dov1) fused skip; compact M=K1 -> h4 (scatter)
    agg_half_kernel<<<K1, FH / 4>>>(p_hbot, p_hid1, p_dov1, nullptr, p_div1, p_al1,
                                    p_xh, p_xl, FH);
    gemm_kernel<1><<<gK1, 256, GEMM_SMEM>>>(p_xh, p_xl, nullptr, nullptr,
                                            p_wth + WO_DEC0, p_wtl + WO_DEC0, p_h4,
                                            K1, FH, FH, p_al1, b_dec0, nullptr, 1);

    // L5: GEMM first with fused (h4+hid0), rowmul=rsqrt(degout); then agg + bias -> out
    gemm_kernel<0><<<gFull128, 256, GEMM_SMEM>>>(nullptr, nullptr, p_h4, p_hid0,
                                                 p_wth + WO_DEC1, p_wtl + WO_DEC1, p_xa,
                                                 NN, FH, FI, nullptr, nullptr, p_degout, 0);
    agg_out_kernel<<<NN, FI / 4>>>(p_xa, b_dec1, out, FI);
}